// round 15
// baseline (speedup 1.0000x reference)
#include <cuda_runtime.h>
#include <cuda_bf16.h>
#include <cstdint>

// Problem constants
#define B_  16
#define C_  512
#define N_  1024
#define D_  64

// Scratch (device globals per allocation rules): 4 + 4 + 32 + 64 = 104 MB
__device__ float g_q[(size_t)B_ * N_ * D_];              // [b][n][d]
__device__ float g_k[(size_t)B_ * N_ * D_];              // [b][n][d]
__device__ float g_v[(size_t)B_ * N_ * C_];              // vT: [b][m][c]
__device__ float g_attn[(size_t)B_ * N_ * N_];           // [b][n][m]

typedef unsigned long long ull;

__device__ __forceinline__ ull pk2(float lo, float hi) {
    ull r; asm("mov.b64 %0, {%1, %2};" : "=l"(r) : "f"(lo), "f"(hi)); return r;
}
__device__ __forceinline__ float2 up2(ull v) {
    float2 r; asm("mov.b64 {%0, %1}, %2;" : "=f"(r.x), "=f"(r.y) : "l"(v)); return r;
}
__device__ __forceinline__ void fma2(ull& d, ull a, ull b) {
    asm("fma.rn.f32x2 %0, %1, %2, %0;" : "+l"(d) : "l"(a), "l"(b));
}

// ---------------------------------------------------------------------------
// Kernel 1: fused QKV projection.  Y[oc, n] = sum_c W[oc,c] * x[b,c,n] + bias
// Tile: 64 oc x 64 n, block 256 threads, 4x4 micro-tile, k-chunks of 16.
// oc0 = 0   -> Wq -> g_q   [b][n][0..64)
// oc0 = 64  -> Wk -> g_k   [b][n][0..64)
// oc0 >=128 -> Wv -> g_v   [b][n][oc0-128 ..)
// ---------------------------------------------------------------------------
__global__ __launch_bounds__(256) void k_proj(
    const float* __restrict__ x,
    const float* __restrict__ Wq, const float* __restrict__ bq,
    const float* __restrict__ Wk, const float* __restrict__ bk,
    const float* __restrict__ Wv, const float* __restrict__ bv)
{
    __shared__ float sA[16][132];  // W tile, value-duplicated: [kk][2*ocl {lo,hi}]
    __shared__ float sB[16][68];   // x tile: [kk][nl]
    __shared__ float sO[64][65];   // output restage [nl][ocl]

    const int b   = blockIdx.z;
    const int oc0 = blockIdx.y * 64;
    const int n0  = blockIdx.x * 64;

    const float* Wsrc; const float* bias; float* dst; int dstride;
    if (oc0 == 0)       { Wsrc = Wq; bias = bq; dst = g_q + (size_t)b * N_ * D_; dstride = D_; }
    else if (oc0 == 64) { Wsrc = Wk; bias = bk; dst = g_k + (size_t)b * N_ * D_; dstride = D_; }
    else                { Wsrc = Wv + (size_t)(oc0 - 128) * C_; bias = bv + (oc0 - 128);
                          dst = g_v + (size_t)b * N_ * C_ + (oc0 - 128); dstride = C_; }

    const int t  = threadIdx.x;
    const int tx = t & 15, ty = t >> 4;

    // load mappings
    const int la_r = t >> 2;          // 0..63  W row within tile
    const int la_c = (t & 3) * 4;     // kk base
    const int lb_k = t >> 4;          // 0..15
    const int lb_n = (t & 15) * 4;    // 0,4,..,60

    const float* xb = x + (size_t)b * C_ * N_ + n0;

    ull acc[4][2];
#pragma unroll
    for (int i = 0; i < 4; ++i) { acc[i][0] = 0ULL; acc[i][1] = 0ULL; }

    for (int k0 = 0; k0 < C_; k0 += 16) {
        float4 w4 = *(const float4*)(Wsrc + (size_t)la_r * C_ + k0 + la_c);
        *(ull*)&sA[la_c + 0][2 * la_r] = pk2(w4.x, w4.x);
        *(ull*)&sA[la_c + 1][2 * la_r] = pk2(w4.y, w4.y);
        *(ull*)&sA[la_c + 2][2 * la_r] = pk2(w4.z, w4.z);
        *(ull*)&sA[la_c + 3][2 * la_r] = pk2(w4.w, w4.w);
        float4 x4 = *(const float4*)(xb + (size_t)(k0 + lb_k) * N_ + lb_n);
        *(float4*)&sB[lb_k][lb_n] = x4;
        __syncthreads();
#pragma unroll
        for (int kk = 0; kk < 16; ++kk) {
            const ull* ap = (const ull*)&sA[kk][ty * 8];
            const ull* bp = (const ull*)&sB[kk][tx * 4];
            ull b0 = bp[0], b1 = bp[1];
#pragma unroll
            for (int i = 0; i < 4; ++i) {
                ull a = ap[i];
                fma2(acc[i][0], a, b0);
                fma2(acc[i][1], a, b1);
            }
        }
        __syncthreads();
    }

    // bias + restage to smem for coalesced transposed write
    float4 bi4 = *(const float4*)(bias + ty * 4);
    float bia[4] = {bi4.x, bi4.y, bi4.z, bi4.w};
#pragma unroll
    for (int i = 0; i < 4; ++i) {
        float2 a0 = up2(acc[i][0]);
        float2 a1 = up2(acc[i][1]);
        sO[tx * 4 + 0][ty * 4 + i] = a0.x + bia[i];
        sO[tx * 4 + 1][ty * 4 + i] = a0.y + bia[i];
        sO[tx * 4 + 2][ty * 4 + i] = a1.x + bia[i];
        sO[tx * 4 + 3][ty * 4 + i] = a1.y + bia[i];
    }
    __syncthreads();
#pragma unroll
    for (int s = 0; s < 16; ++s) {
        int idx = s * 256 + t;
        int nl  = idx >> 6;
        int ocl = idx & 63;
        dst[(size_t)(n0 + nl) * dstride + ocl] = sO[nl][ocl];
    }
}

// ---------------------------------------------------------------------------
// Kernel 2: scores S[b,n,m] = sum_d q[b,n,d] * k[b,m,d]   (NT GEMM, K=64)
// ---------------------------------------------------------------------------
__global__ __launch_bounds__(256) void k_scores()
{
    __shared__ float sA[16][132];  // q tile duplicated: [kk][2*nl]
    __shared__ float sB[16][68];   // k tile transposed: [kk][ml]

    const int b  = blockIdx.z;
    const int n0 = blockIdx.y * 64;
    const int m0 = blockIdx.x * 64;

    const int t  = threadIdx.x;
    const int tx = t & 15, ty = t >> 4;
    const int lr = t >> 2;          // 0..63 row within tile
    const int lc = (t & 3) * 4;     // kk base

    const float* qb = g_q + (size_t)b * N_ * D_;
    const float* kb = g_k + (size_t)b * N_ * D_;

    ull acc[4][2];
#pragma unroll
    for (int i = 0; i < 4; ++i) { acc[i][0] = 0ULL; acc[i][1] = 0ULL; }

    for (int k0 = 0; k0 < D_; k0 += 16) {
        float4 q4 = *(const float4*)(qb + (size_t)(n0 + lr) * D_ + k0 + lc);
        *(ull*)&sA[lc + 0][2 * lr] = pk2(q4.x, q4.x);
        *(ull*)&sA[lc + 1][2 * lr] = pk2(q4.y, q4.y);
        *(ull*)&sA[lc + 2][2 * lr] = pk2(q4.z, q4.z);
        *(ull*)&sA[lc + 3][2 * lr] = pk2(q4.w, q4.w);
        float4 k4 = *(const float4*)(kb + (size_t)(m0 + lr) * D_ + k0 + lc);
        sB[lc + 0][lr] = k4.x;
        sB[lc + 1][lr] = k4.y;
        sB[lc + 2][lr] = k4.z;
        sB[lc + 3][lr] = k4.w;
        __syncthreads();
#pragma unroll
        for (int kk = 0; kk < 16; ++kk) {
            const ull* ap = (const ull*)&sA[kk][ty * 8];
            const ull* bp = (const ull*)&sB[kk][tx * 4];
            ull b0 = bp[0], b1 = bp[1];
#pragma unroll
            for (int i = 0; i < 4; ++i) {
                ull a = ap[i];
                fma2(acc[i][0], a, b0);
                fma2(acc[i][1], a, b1);
            }
        }
        __syncthreads();
    }

    float* Sb = g_attn + (size_t)b * N_ * N_;
#pragma unroll
    for (int i = 0; i < 4; ++i) {
        float2 a0 = up2(acc[i][0]);
        float2 a1 = up2(acc[i][1]);
        *(float4*)(Sb + (size_t)(n0 + ty * 4 + i) * N_ + m0 + tx * 4) =
            make_float4(a0.x, a0.y, a1.x, a1.y);
    }
}

// ---------------------------------------------------------------------------
// Kernel 3: row softmax over g_attn, in place. One block per (b, n) row.
// ---------------------------------------------------------------------------
__global__ __launch_bounds__(256) void k_softmax()
{
    float* p = g_attn + (size_t)blockIdx.x * N_;
    const int t = threadIdx.x;
    const int w = t >> 5, l = t & 31;
    __shared__ float red[8];

    float4 v = *(float4*)(p + t * 4);
    float m = fmaxf(fmaxf(v.x, v.y), fmaxf(v.z, v.w));
#pragma unroll
    for (int o = 16; o; o >>= 1) m = fmaxf(m, __shfl_xor_sync(0xffffffffu, m, o));
    if (l == 0) red[w] = m;
    __syncthreads();
    if (t == 0) {
        float mm = red[0];
#pragma unroll
        for (int i = 1; i < 8; ++i) mm = fmaxf(mm, red[i]);
        red[0] = mm;
    }
    __syncthreads();
    const float M = red[0];
    __syncthreads();

    v.x = __expf(v.x - M);
    v.y = __expf(v.y - M);
    v.z = __expf(v.z - M);
    v.w = __expf(v.w - M);
    float s = v.x + v.y + v.z + v.w;
#pragma unroll
    for (int o = 16; o; o >>= 1) s += __shfl_xor_sync(0xffffffffu, s, o);
    if (l == 0) red[w] = s;
    __syncthreads();
    if (t == 0) {
        float ss = red[0];
#pragma unroll
        for (int i = 1; i < 8; ++i) ss += red[i];
        red[0] = ss;
    }
    __syncthreads();
    const float inv = 1.0f / red[0];

    v.x *= inv; v.y *= inv; v.z *= inv; v.w *= inv;
    *(float4*)(p + t * 4) = v;
}

// ---------------------------------------------------------------------------
// Kernel 4: out[b,c,n] = gamma * sum_m attn[b,n,m] * vT[b,m,c] + x[b,c,n]
// Computed as O_T[c][n]: rows = c (from vT, contiguous dup load),
// cols = n (from attn, transposed load). Direct coalesced float4 epilogue.
// ---------------------------------------------------------------------------
__global__ __launch_bounds__(256) void k_out(
    const float* __restrict__ x, const float* __restrict__ gamma,
    float* __restrict__ out)
{
    __shared__ float sA[16][132];  // vT tile duplicated: [kk][2*cl]
    __shared__ float sB[16][68];   // attn tile transposed: [kk][nl]

    const int b  = blockIdx.z;
    const int c0 = blockIdx.y * 64;
    const int n0 = blockIdx.x * 64;

    const int t  = threadIdx.x;
    const int tx = t & 15, ty = t >> 4;

    // vT load mapping (contiguous in c)
    const int va_k = t >> 4;          // 0..15
    const int va_c = (t & 15) * 4;    // 0,4,..,60
    // attn load mapping (transposed)
    const int ab_n = t >> 2;          // 0..63
    const int ab_k = (t & 3) * 4;     // kk base

    const float* vb = g_v    + (size_t)b * N_ * C_ + c0;
    const float* Ab = g_attn + (size_t)b * N_ * N_;

    ull acc[4][2];
#pragma unroll
    for (int i = 0; i < 4; ++i) { acc[i][0] = 0ULL; acc[i][1] = 0ULL; }

    for (int k0 = 0; k0 < N_; k0 += 16) {
        float4 v4 = *(const float4*)(vb + (size_t)(k0 + va_k) * C_ + va_c);
        *(float4*)&sA[va_k][2 * va_c]     = make_float4(v4.x, v4.x, v4.y, v4.y);
        *(float4*)&sA[va_k][2 * va_c + 4] = make_float4(v4.z, v4.z, v4.w, v4.w);
        float4 a4 = *(const float4*)(Ab + (size_t)(n0 + ab_n) * N_ + k0 + ab_k);
        sB[ab_k + 0][ab_n] = a4.x;
        sB[ab_k + 1][ab_n] = a4.y;
        sB[ab_k + 2][ab_n] = a4.z;
        sB[ab_k + 3][ab_n] = a4.w;
        __syncthreads();
#pragma unroll
        for (int kk = 0; kk < 16; ++kk) {
            const ull* ap = (const ull*)&sA[kk][ty * 8];
            const ull* bp = (const ull*)&sB[kk][tx * 4];
            ull b0 = bp[0], b1 = bp[1];
#pragma unroll
            for (int i = 0; i < 4; ++i) {
                ull a = ap[i];
                fma2(acc[i][0], a, b0);
                fma2(acc[i][1], a, b1);
            }
        }
        __syncthreads();
    }

    const float gm = gamma[0];
#pragma unroll
    for (int i = 0; i < 4; ++i) {
        int c = c0 + ty * 4 + i;
        size_t off = ((size_t)b * C_ + c) * N_ + n0 + tx * 4;
        float4 xv = *(const float4*)(x + off);
        float2 a0 = up2(acc[i][0]);
        float2 a1 = up2(acc[i][1]);
        float4 o;
        o.x = fmaf(gm, a0.x, xv.x);
        o.y = fmaf(gm, a0.y, xv.y);
        o.z = fmaf(gm, a1.x, xv.z);
        o.w = fmaf(gm, a1.y, xv.w);
        *(float4*)(out + off) = o;
    }
}

// ---------------------------------------------------------------------------
extern "C" void kernel_launch(void* const* d_in, const int* in_sizes, int n_in,
                              void* d_out, int out_size)
{
    (void)in_sizes; (void)n_in; (void)out_size;
    const float* x     = (const float*)d_in[0];
    const float* Wq    = (const float*)d_in[1];
    const float* bq    = (const float*)d_in[2];
    const float* Wk    = (const float*)d_in[3];
    const float* bk    = (const float*)d_in[4];
    const float* Wv    = (const float*)d_in[5];
    const float* bv    = (const float*)d_in[6];
    const float* gamma = (const float*)d_in[7];
    float* out = (float*)d_out;

    k_proj<<<dim3(N_ / 64, 10, B_), 256>>>(x, Wq, bq, Wk, bk, Wv, bv);
    k_scores<<<dim3(N_ / 64, N_ / 64, B_), 256>>>();
    k_softmax<<<B_ * N_, 256>>>();
    k_out<<<dim3(N_ / 64, C_ / 64, B_), 256>>>(x, gamma, out);
}

// round 16
// speedup vs baseline: 1.0278x; 1.0278x over previous
#include <cuda_runtime.h>
#include <cuda_bf16.h>
#include <cstdint>

// Problem constants
#define B_  16
#define C_  512
#define N_  1024
#define D_  64

// Scratch (device globals per allocation rules): 4 + 4 + 32 + 64 = 104 MB
__device__ float g_q[(size_t)B_ * N_ * D_];              // [b][n][d]
__device__ float g_k[(size_t)B_ * N_ * D_];              // [b][n][d]
__device__ float g_v[(size_t)B_ * N_ * C_];              // vT: [b][n][c]
__device__ float g_attn[(size_t)B_ * N_ * N_];           // [b][n][m]

typedef unsigned long long ull;

__device__ __forceinline__ ull pk2(float lo, float hi) {
    ull r; asm("mov.b64 %0, {%1, %2};" : "=l"(r) : "f"(lo), "f"(hi)); return r;
}
__device__ __forceinline__ float2 up2(ull v) {
    float2 r; asm("mov.b64 {%0, %1}, %2;" : "=f"(r.x), "=f"(r.y) : "l"(v)); return r;
}
__device__ __forceinline__ void fma2(ull& d, ull a, ull b) {
    asm("fma.rn.f32x2 %0, %1, %2, %0;" : "+l"(d) : "l"(a), "l"(b));
}

// Shared-tile strides (floats). sA holds duplicated A pairs: 256 + pad.
#define SA_STR 268
#define SB_STR 136

// Shared inner-product body: 16 k-steps, 32 FFMA2 each, 6 LDS.128 each.
#define MAINLOOP_16(acc, sA, sB, ty, tx)                                   \
    _Pragma("unroll")                                                       \
    for (int kk = 0; kk < 16; ++kk) {                                       \
        const ull* ap = (const ull*)&sA[kk][(ty) * 16];                     \
        const ull* bp = (const ull*)&sB[kk][(tx) * 8];                      \
        ull a0 = ap[0], a1 = ap[1], a2 = ap[2], a3 = ap[3];                 \
        ull a4 = ap[4], a5 = ap[5], a6 = ap[6], a7 = ap[7];                 \
        ull b0 = bp[0], b1 = bp[1], b2 = bp[2], b3 = bp[3];                 \
        fma2(acc[0][0], a0, b0); fma2(acc[0][1], a0, b1);                   \
        fma2(acc[0][2], a0, b2); fma2(acc[0][3], a0, b3);                   \
        fma2(acc[1][0], a1, b0); fma2(acc[1][1], a1, b1);                   \
        fma2(acc[1][2], a1, b2); fma2(acc[1][3], a1, b3);                   \
        fma2(acc[2][0], a2, b0); fma2(acc[2][1], a2, b1);                   \
        fma2(acc[2][2], a2, b2); fma2(acc[2][3], a2, b3);                   \
        fma2(acc[3][0], a3, b0); fma2(acc[3][1], a3, b1);                   \
        fma2(acc[3][2], a3, b2); fma2(acc[3][3], a3, b3);                   \
        fma2(acc[4][0], a4, b0); fma2(acc[4][1], a4, b1);                   \
        fma2(acc[4][2], a4, b2); fma2(acc[4][3], a4, b3);                   \
        fma2(acc[5][0], a5, b0); fma2(acc[5][1], a5, b1);                   \
        fma2(acc[5][2], a5, b2); fma2(acc[5][3], a5, b3);                   \
        fma2(acc[6][0], a6, b0); fma2(acc[6][1], a6, b1);                   \
        fma2(acc[6][2], a6, b2); fma2(acc[6][3], a6, b3);                   \
        fma2(acc[7][0], a7, b0); fma2(acc[7][1], a7, b1);                   \
        fma2(acc[7][2], a7, b2); fma2(acc[7][3], a7, b3);                   \
    }

// Duplicated float4 store helper for A-staging from a contiguous source.
__device__ __forceinline__ void store_dup8(float* row, int col2, float4 v0, float4 v1) {
    *(float4*)&row[col2 +  0] = make_float4(v0.x, v0.x, v0.y, v0.y);
    *(float4*)&row[col2 +  4] = make_float4(v0.z, v0.z, v0.w, v0.w);
    *(float4*)&row[col2 +  8] = make_float4(v1.x, v1.x, v1.y, v1.y);
    *(float4*)&row[col2 + 12] = make_float4(v1.z, v1.z, v1.w, v1.w);
}

// ---------------------------------------------------------------------------
// Kernel 1: fused QKV projection, output-transposed.
//   Y[n][oc] = sum_c x[b][c][n] * W[oc][c] + bias[oc]
// Tile 128(n) x 128(oc). oy==0 -> oc 0..63 = Q, 64..127 = K. oy>=1 -> V.
// A (dup operand) = x : n-contiguous -> vector dup staging.
// B = W : c-contiguous per oc row -> transpose staging.
// ---------------------------------------------------------------------------
__global__ __launch_bounds__(256, 2) void k_proj(
    const float* __restrict__ x,
    const float* __restrict__ Wq, const float* __restrict__ bq,
    const float* __restrict__ Wk, const float* __restrict__ bk,
    const float* __restrict__ Wv, const float* __restrict__ bv)
{
    __shared__ float sA[16][SA_STR];
    __shared__ float sB[16][SB_STR];

    const int b  = blockIdx.z;
    const int oy = blockIdx.y;
    const int n0 = blockIdx.x * 128;

    const int t  = threadIdx.x;
    const int tx = t & 15, ty = t >> 4;

    // A staging map: contiguous dup
    const int la_k = t >> 4;          // 0..15
    const int la_n = (t & 15) * 8;    // 0..120
    // B staging map: transpose
    const int lb_o = t >> 1;          // ocl 0..127
    const int lb_k = (t & 1) * 8;     // 0 or 8

    const float* xb = x + (size_t)b * C_ * N_ + n0;

    // per-thread W row pointer (loop invariant)
    const float* wrow;
    if (oy == 0) wrow = (lb_o < 64) ? (Wq + (size_t)lb_o * C_)
                                    : (Wk + (size_t)(lb_o - 64) * C_);
    else         wrow = Wv + (size_t)((oy - 1) * 128 + lb_o) * C_;

    ull acc[8][4];
#pragma unroll
    for (int i = 0; i < 8; ++i)
#pragma unroll
        for (int j = 0; j < 4; ++j) acc[i][j] = 0ULL;

    for (int k0 = 0; k0 < C_; k0 += 16) {
        const float* ap = xb + (size_t)(k0 + la_k) * N_ + la_n;
        float4 v0 = *(const float4*)(ap);
        float4 v1 = *(const float4*)(ap + 4);
        store_dup8(&sA[la_k][0], 2 * la_n, v0, v1);

        const float* bp = wrow + k0 + lb_k;
        float4 u0 = *(const float4*)(bp);
        float4 u1 = *(const float4*)(bp + 4);
        sB[lb_k + 0][lb_o] = u0.x;
        sB[lb_k + 1][lb_o] = u0.y;
        sB[lb_k + 2][lb_o] = u0.z;
        sB[lb_k + 3][lb_o] = u0.w;
        sB[lb_k + 4][lb_o] = u1.x;
        sB[lb_k + 5][lb_o] = u1.y;
        sB[lb_k + 6][lb_o] = u1.z;
        sB[lb_k + 7][lb_o] = u1.w;
        __syncthreads();

        MAINLOOP_16(acc, sA, sB, ty, tx)
        __syncthreads();
    }

    // epilogue: thread owns oc columns tx*8..tx*8+7, rows n0+ty*8+i
    float* dst; const float* bias; int ocb; int ds;
    if (oy == 0) {
        if (tx < 8) { dst = g_q + (size_t)b * N_ * D_; bias = bq; ocb = tx * 8;      ds = D_; }
        else        { dst = g_k + (size_t)b * N_ * D_; bias = bk; ocb = tx * 8 - 64; ds = D_; }
    } else {
        dst  = g_v + (size_t)b * N_ * C_ + (oy - 1) * 128;
        bias = bv + (oy - 1) * 128;
        ocb  = tx * 8; ds = C_;
    }
    float4 bi0 = *(const float4*)(bias + (oy == 0 ? ocb : tx * 8));
    float4 bi1 = *(const float4*)(bias + (oy == 0 ? ocb : tx * 8) + 4);

#pragma unroll
    for (int i = 0; i < 8; ++i) {
        int n = n0 + ty * 8 + i;
        float2 p0 = up2(acc[i][0]), p1 = up2(acc[i][1]);
        float2 p2 = up2(acc[i][2]), p3 = up2(acc[i][3]);
        float* o = dst + (size_t)n * ds + ocb;
        *(float4*)(o)     = make_float4(p0.x + bi0.x, p0.y + bi0.y, p1.x + bi0.z, p1.y + bi0.w);
        *(float4*)(o + 4) = make_float4(p2.x + bi1.x, p2.y + bi1.y, p3.x + bi1.z, p3.y + bi1.w);
    }
}

// ---------------------------------------------------------------------------
// Kernel 2: scores S[b,n,m] = sum_d q[b,n,d] * k[b,m,d]   (NT GEMM, K=64)
// Tile 128(n) x 128(m). Both operands d-contiguous -> transpose staging.
// ---------------------------------------------------------------------------
__global__ __launch_bounds__(256, 2) void k_scores()
{
    __shared__ float sA[16][SA_STR];
    __shared__ float sB[16][SB_STR];

    const int b  = blockIdx.z;
    const int n0 = blockIdx.y * 128;
    const int m0 = blockIdx.x * 128;

    const int t  = threadIdx.x;
    const int tx = t & 15, ty = t >> 4;
    const int lr = t >> 1;            // row within tile 0..127
    const int lk = (t & 1) * 8;       // k base

    const float* qb = g_q + (size_t)b * N_ * D_;
    const float* kb = g_k + (size_t)b * N_ * D_;

    ull acc[8][4];
#pragma unroll
    for (int i = 0; i < 8; ++i)
#pragma unroll
        for (int j = 0; j < 4; ++j) acc[i][j] = 0ULL;

    for (int k0 = 0; k0 < D_; k0 += 16) {
        const float* ap = qb + (size_t)(n0 + lr) * D_ + k0 + lk;
        float4 q0 = *(const float4*)(ap);
        float4 q1 = *(const float4*)(ap + 4);
        *(ull*)&sA[lk + 0][2 * lr] = pk2(q0.x, q0.x);
        *(ull*)&sA[lk + 1][2 * lr] = pk2(q0.y, q0.y);
        *(ull*)&sA[lk + 2][2 * lr] = pk2(q0.z, q0.z);
        *(ull*)&sA[lk + 3][2 * lr] = pk2(q0.w, q0.w);
        *(ull*)&sA[lk + 4][2 * lr] = pk2(q1.x, q1.x);
        *(ull*)&sA[lk + 5][2 * lr] = pk2(q1.y, q1.y);
        *(ull*)&sA[lk + 6][2 * lr] = pk2(q1.z, q1.z);
        *(ull*)&sA[lk + 7][2 * lr] = pk2(q1.w, q1.w);

        const float* bp = kb + (size_t)(m0 + lr) * D_ + k0 + lk;
        float4 k0v = *(const float4*)(bp);
        float4 k1v = *(const float4*)(bp + 4);
        sB[lk + 0][lr] = k0v.x;
        sB[lk + 1][lr] = k0v.y;
        sB[lk + 2][lr] = k0v.z;
        sB[lk + 3][lr] = k0v.w;
        sB[lk + 4][lr] = k1v.x;
        sB[lk + 5][lr] = k1v.y;
        sB[lk + 6][lr] = k1v.z;
        sB[lk + 7][lr] = k1v.w;
        __syncthreads();

        MAINLOOP_16(acc, sA, sB, ty, tx)
        __syncthreads();
    }

    float* Sb = g_attn + (size_t)b * N_ * N_;
#pragma unroll
    for (int i = 0; i < 8; ++i) {
        float2 p0 = up2(acc[i][0]), p1 = up2(acc[i][1]);
        float2 p2 = up2(acc[i][2]), p3 = up2(acc[i][3]);
        float* o = Sb + (size_t)(n0 + ty * 8 + i) * N_ + m0 + tx * 8;
        *(float4*)(o)     = make_float4(p0.x, p0.y, p1.x, p1.y);
        *(float4*)(o + 4) = make_float4(p2.x, p2.y, p3.x, p3.y);
    }
}

// ---------------------------------------------------------------------------
// Kernel 3: row softmax over g_attn, in place. One block per (b, n) row.
// ---------------------------------------------------------------------------
__global__ __launch_bounds__(256) void k_softmax()
{
    float* p = g_attn + (size_t)blockIdx.x * N_;
    const int t = threadIdx.x;
    const int w = t >> 5, l = t & 31;
    __shared__ float red[8];

    float4 v = *(float4*)(p + t * 4);
    float m = fmaxf(fmaxf(v.x, v.y), fmaxf(v.z, v.w));
#pragma unroll
    for (int o = 16; o; o >>= 1) m = fmaxf(m, __shfl_xor_sync(0xffffffffu, m, o));
    if (l == 0) red[w] = m;
    __syncthreads();
    if (t == 0) {
        float mm = red[0];
#pragma unroll
        for (int i = 1; i < 8; ++i) mm = fmaxf(mm, red[i]);
        red[0] = mm;
    }
    __syncthreads();
    const float M = red[0];
    __syncthreads();

    v.x = __expf(v.x - M);
    v.y = __expf(v.y - M);
    v.z = __expf(v.z - M);
    v.w = __expf(v.w - M);
    float s = v.x + v.y + v.z + v.w;
#pragma unroll
    for (int o = 16; o; o >>= 1) s += __shfl_xor_sync(0xffffffffu, s, o);
    if (l == 0) red[w] = s;
    __syncthreads();
    if (t == 0) {
        float ss = red[0];
#pragma unroll
        for (int i = 1; i < 8; ++i) ss += red[i];
        red[0] = ss;
    }
    __syncthreads();
    const float inv = 1.0f / red[0];

    v.x *= inv; v.y *= inv; v.z *= inv; v.w *= inv;
    *(float4*)(p + t * 4) = v;
}

// ---------------------------------------------------------------------------
// Kernel 4: out[b,c,n] = gamma * sum_m attn[b,n,m] * vT[b,m,c] + x[b,c,n]
// Tile 128(c) x 128(n), K = N_ = 1024.
// A (dup) = vT : c-contiguous -> vector dup staging.
// B = attn : m(k)-contiguous per n row -> transpose staging.
// ---------------------------------------------------------------------------
__global__ __launch_bounds__(256, 2) void k_out(
    const float* __restrict__ x, const float* __restrict__ gamma,
    float* __restrict__ out)
{
    __shared__ float sA[16][SA_STR];
    __shared__ float sB[16][SB_STR];

    const int b  = blockIdx.z;
    const int c0 = blockIdx.y * 128;
    const int n0 = blockIdx.x * 128;

    const int t  = threadIdx.x;
    const int tx = t & 15, ty = t >> 4;

    const int la_k = t >> 4;          // 0..15
    const int la_c = (t & 15) * 8;    // 0..120
    const int lb_n = t >> 1;          // 0..127
    const int lb_k = (t & 1) * 8;     // 0 or 8

    const float* vb = g_v    + (size_t)b * N_ * C_ + c0;
    const float* Ab = g_attn + (size_t)b * N_ * N_ + (size_t)(n0 + lb_n) * N_ + lb_k;

    ull acc[8][4];
#pragma unroll
    for (int i = 0; i < 8; ++i)
#pragma unroll
        for (int j = 0; j < 4; ++j) acc[i][j] = 0ULL;

    for (int k0 = 0; k0 < N_; k0 += 16) {
        const float* ap = vb + (size_t)(k0 + la_k) * C_ + la_c;
        float4 v0 = *(const float4*)(ap);
        float4 v1 = *(const float4*)(ap + 4);
        store_dup8(&sA[la_k][0], 2 * la_c, v0, v1);

        const float* bp = Ab + k0;
        float4 a0 = *(const float4*)(bp);
        float4 a1 = *(const float4*)(bp + 4);
        sB[lb_k + 0][lb_n] = a0.x;
        sB[lb_k + 1][lb_n] = a0.y;
        sB[lb_k + 2][lb_n] = a0.z;
        sB[lb_k + 3][lb_n] = a0.w;
        sB[lb_k + 4][lb_n] = a1.x;
        sB[lb_k + 5][lb_n] = a1.y;
        sB[lb_k + 6][lb_n] = a1.z;
        sB[lb_k + 7][lb_n] = a1.w;
        __syncthreads();

        MAINLOOP_16(acc, sA, sB, ty, tx)
        __syncthreads();
    }

    const float gm = gamma[0];
#pragma unroll
    for (int i = 0; i < 8; ++i) {
        int c = c0 + ty * 8 + i;
        size_t off = ((size_t)b * C_ + c) * N_ + n0 + tx * 8;
        float4 x0 = *(const float4*)(x + off);
        float4 x1 = *(const float4*)(x + off + 4);
        float2 p0 = up2(acc[i][0]), p1 = up2(acc[i][1]);
        float2 p2 = up2(acc[i][2]), p3 = up2(acc[i][3]);
        float4 o0, o1;
        o0.x = fmaf(gm, p0.x, x0.x);
        o0.y = fmaf(gm, p0.y, x0.y);
        o0.z = fmaf(gm, p1.x, x0.z);
        o0.w = fmaf(gm, p1.y, x0.w);
        o1.x = fmaf(gm, p2.x, x1.x);
        o1.y = fmaf(gm, p2.y, x1.y);
        o1.z = fmaf(gm, p3.x, x1.z);
        o1.w = fmaf(gm, p3.y, x1.w);
        *(float4*)(out + off)     = o0;
        *(float4*)(out + off + 4) = o1;
    }
}

// ---------------------------------------------------------------------------
extern "C" void kernel_launch(void* const* d_in, const int* in_sizes, int n_in,
                              void* d_out, int out_size)
{
    (void)in_sizes; (void)n_in; (void)out_size;
    const float* x     = (const float*)d_in[0];
    const float* Wq    = (const float*)d_in[1];
    const float* bq    = (const float*)d_in[2];
    const float* Wk    = (const float*)d_in[3];
    const float* bk    = (const float*)d_in[4];
    const float* Wv    = (const float*)d_in[5];
    const float* bv    = (const float*)d_in[6];
    const float* gamma = (const float*)d_in[7];
    float* out = (float*)d_out;

    k_proj  <<<dim3(N_ / 128, 5,        B_), 256>>>(x, Wq, bq, Wk, bk, Wv, bv);
    k_scores<<<dim3(N_ / 128, N_ / 128, B_), 256>>>();
    k_softmax<<<B_ * N_, 256>>>();
    k_out   <<<dim3(N_ / 128, C_ / 128, B_), 256>>>(x, gamma, out);
}

// round 17
// speedup vs baseline: 1.0282x; 1.0004x over previous
#include <cuda_runtime.h>
#include <cuda_bf16.h>
#include <cstdint>

// Problem constants
#define B_  16
#define C_  512
#define N_  1024
#define D_  64

// Scratch (device globals per allocation rules): 4 + 4 + 32 + 64 = 104 MB
__device__ float g_q[(size_t)B_ * N_ * D_];              // [b][n][d]
__device__ float g_k[(size_t)B_ * N_ * D_];              // [b][n][d]
__device__ float g_v[(size_t)B_ * N_ * C_];              // vT: [b][n][c]
__device__ float g_attn[(size_t)B_ * N_ * N_];           // [b][n][m]

typedef unsigned long long ull;

__device__ __forceinline__ ull pk2(float lo, float hi) {
    ull r; asm("mov.b64 %0, {%1, %2};" : "=l"(r) : "f"(lo), "f"(hi)); return r;
}
__device__ __forceinline__ float2 up2(ull v) {
    float2 r; asm("mov.b64 {%0, %1}, %2;" : "=f"(r.x), "=f"(r.y) : "l"(v)); return r;
}
__device__ __forceinline__ void fma2(ull& d, ull a, ull b) {
    asm("fma.rn.f32x2 %0, %1, %2, %0;" : "+l"(d) : "l"(a), "l"(b));
}

// Shared-tile strides (floats). sA holds duplicated A pairs: 256 + pad.
#define SA_STR 268
#define SB_STR 136

// Shared inner-product body: 16 k-steps, 32 FFMA2 each, 6 LDS.128 each.
#define MAINLOOP_16(acc, sA, sB, ty, tx)                                   \
    _Pragma("unroll")                                                       \
    for (int kk = 0; kk < 16; ++kk) {                                       \
        const ull* ap = (const ull*)&sA[kk][(ty) * 16];                     \
        const ull* bp = (const ull*)&sB[kk][(tx) * 8];                      \
        ull a0 = ap[0], a1 = ap[1], a2 = ap[2], a3 = ap[3];                 \
        ull a4 = ap[4], a5 = ap[5], a6 = ap[6], a7 = ap[7];                 \
        ull b0 = bp[0], b1 = bp[1], b2 = bp[2], b3 = bp[3];                 \
        fma2(acc[0][0], a0, b0); fma2(acc[0][1], a0, b1);                   \
        fma2(acc[0][2], a0, b2); fma2(acc[0][3], a0, b3);                   \
        fma2(acc[1][0], a1, b0); fma2(acc[1][1], a1, b1);                   \
        fma2(acc[1][2], a1, b2); fma2(acc[1][3], a1, b3);                   \
        fma2(acc[2][0], a2, b0); fma2(acc[2][1], a2, b1);                   \
        fma2(acc[2][2], a2, b2); fma2(acc[2][3], a2, b3);                   \
        fma2(acc[3][0], a3, b0); fma2(acc[3][1], a3, b1);                   \
        fma2(acc[3][2], a3, b2); fma2(acc[3][3], a3, b3);                   \
        fma2(acc[4][0], a4, b0); fma2(acc[4][1], a4, b1);                   \
        fma2(acc[4][2], a4, b2); fma2(acc[4][3], a4, b3);                   \
        fma2(acc[5][0], a5, b0); fma2(acc[5][1], a5, b1);                   \
        fma2(acc[5][2], a5, b2); fma2(acc[5][3], a5, b3);                   \
        fma2(acc[6][0], a6, b0); fma2(acc[6][1], a6, b1);                   \
        fma2(acc[6][2], a6, b2); fma2(acc[6][3], a6, b3);                   \
        fma2(acc[7][0], a7, b0); fma2(acc[7][1], a7, b1);                   \
        fma2(acc[7][2], a7, b2); fma2(acc[7][3], a7, b3);                   \
    }

// Duplicated float4 store helper for A-staging from a contiguous source.
__device__ __forceinline__ void store_dup8(float* row, int col2, float4 v0, float4 v1) {
    *(float4*)&row[col2 +  0] = make_float4(v0.x, v0.x, v0.y, v0.y);
    *(float4*)&row[col2 +  4] = make_float4(v0.z, v0.z, v0.w, v0.w);
    *(float4*)&row[col2 +  8] = make_float4(v1.x, v1.x, v1.y, v1.y);
    *(float4*)&row[col2 + 12] = make_float4(v1.z, v1.z, v1.w, v1.w);
}

// ---------------------------------------------------------------------------
// Kernel 1: fused QKV projection, output-transposed.
//   Y[n][oc] = sum_c x[b][c][n] * W[oc][c] + bias[oc]
// Tile 128(n) x 128(oc). oy==0 -> oc 0..63 = Q, 64..127 = K. oy>=1 -> V.
// A (dup operand) = x : n-contiguous -> vector dup staging.
// B = W : c-contiguous per oc row -> transpose staging.
// ---------------------------------------------------------------------------
__global__ __launch_bounds__(256, 2) void k_proj(
    const float* __restrict__ x,
    const float* __restrict__ Wq, const float* __restrict__ bq,
    const float* __restrict__ Wk, const float* __restrict__ bk,
    const float* __restrict__ Wv, const float* __restrict__ bv)
{
    __shared__ float sA[16][SA_STR];
    __shared__ float sB[16][SB_STR];

    const int b  = blockIdx.z;
    const int oy = blockIdx.y;
    const int n0 = blockIdx.x * 128;

    const int t  = threadIdx.x;
    const int tx = t & 15, ty = t >> 4;

    // A staging map: contiguous dup
    const int la_k = t >> 4;          // 0..15
    const int la_n = (t & 15) * 8;    // 0..120
    // B staging map: transpose
    const int lb_o = t >> 1;          // ocl 0..127
    const int lb_k = (t & 1) * 8;     // 0 or 8

    const float* xb = x + (size_t)b * C_ * N_ + n0;

    // per-thread W row pointer (loop invariant)
    const float* wrow;
    if (oy == 0) wrow = (lb_o < 64) ? (Wq + (size_t)lb_o * C_)
                                    : (Wk + (size_t)(lb_o - 64) * C_);
    else         wrow = Wv + (size_t)((oy - 1) * 128 + lb_o) * C_;

    ull acc[8][4];
#pragma unroll
    for (int i = 0; i < 8; ++i)
#pragma unroll
        for (int j = 0; j < 4; ++j) acc[i][j] = 0ULL;

    for (int k0 = 0; k0 < C_; k0 += 16) {
        const float* ap = xb + (size_t)(k0 + la_k) * N_ + la_n;
        float4 v0 = *(const float4*)(ap);
        float4 v1 = *(const float4*)(ap + 4);
        store_dup8(&sA[la_k][0], 2 * la_n, v0, v1);

        const float* bp = wrow + k0 + lb_k;
        float4 u0 = *(const float4*)(bp);
        float4 u1 = *(const float4*)(bp + 4);
        sB[lb_k + 0][lb_o] = u0.x;
        sB[lb_k + 1][lb_o] = u0.y;
        sB[lb_k + 2][lb_o] = u0.z;
        sB[lb_k + 3][lb_o] = u0.w;
        sB[lb_k + 4][lb_o] = u1.x;
        sB[lb_k + 5][lb_o] = u1.y;
        sB[lb_k + 6][lb_o] = u1.z;
        sB[lb_k + 7][lb_o] = u1.w;
        __syncthreads();

        MAINLOOP_16(acc, sA, sB, ty, tx)
        __syncthreads();
    }

    // epilogue: thread owns oc columns tx*8..tx*8+7, rows n0+ty*8+i
    float* dst; const float* bias; int ocb; int ds;
    if (oy == 0) {
        if (tx < 8) { dst = g_q + (size_t)b * N_ * D_; bias = bq; ocb = tx * 8;      ds = D_; }
        else        { dst = g_k + (size_t)b * N_ * D_; bias = bk; ocb = tx * 8 - 64; ds = D_; }
    } else {
        dst  = g_v + (size_t)b * N_ * C_ + (oy - 1) * 128;
        bias = bv + (oy - 1) * 128;
        ocb  = tx * 8; ds = C_;
    }
    float4 bi0 = *(const float4*)(bias + (oy == 0 ? ocb : tx * 8));
    float4 bi1 = *(const float4*)(bias + (oy == 0 ? ocb : tx * 8) + 4);

#pragma unroll
    for (int i = 0; i < 8; ++i) {
        int n = n0 + ty * 8 + i;
        float2 p0 = up2(acc[i][0]), p1 = up2(acc[i][1]);
        float2 p2 = up2(acc[i][2]), p3 = up2(acc[i][3]);
        float* o = dst + (size_t)n * ds + ocb;
        *(float4*)(o)     = make_float4(p0.x + bi0.x, p0.y + bi0.y, p1.x + bi0.z, p1.y + bi0.w);
        *(float4*)(o + 4) = make_float4(p2.x + bi1.x, p2.y + bi1.y, p3.x + bi1.z, p3.y + bi1.w);
    }
}

// ---------------------------------------------------------------------------
// Kernel 2: scores S[b,n,m] = sum_d q[b,n,d] * k[b,m,d]   (NT GEMM, K=64)
// Tile 128(n) x 128(m). Both operands d-contiguous -> transpose staging.
// ---------------------------------------------------------------------------
__global__ __launch_bounds__(256, 2) void k_scores()
{
    __shared__ float sA[16][SA_STR];
    __shared__ float sB[16][SB_STR];

    const int b  = blockIdx.z;
    const int n0 = blockIdx.y * 128;
    const int m0 = blockIdx.x * 128;

    const int t  = threadIdx.x;
    const int tx = t & 15, ty = t >> 4;
    const int lr = t >> 1;            // row within tile 0..127
    const int lk = (t & 1) * 8;       // k base

    const float* qb = g_q + (size_t)b * N_ * D_;
    const float* kb = g_k + (size_t)b * N_ * D_;

    ull acc[8][4];
#pragma unroll
    for (int i = 0; i < 8; ++i)
#pragma unroll
        for (int j = 0; j < 4; ++j) acc[i][j] = 0ULL;

    for (int k0 = 0; k0 < D_; k0 += 16) {
        const float* ap = qb + (size_t)(n0 + lr) * D_ + k0 + lk;
        float4 q0 = *(const float4*)(ap);
        float4 q1 = *(const float4*)(ap + 4);
        *(ull*)&sA[lk + 0][2 * lr] = pk2(q0.x, q0.x);
        *(ull*)&sA[lk + 1][2 * lr] = pk2(q0.y, q0.y);
        *(ull*)&sA[lk + 2][2 * lr] = pk2(q0.z, q0.z);
        *(ull*)&sA[lk + 3][2 * lr] = pk2(q0.w, q0.w);
        *(ull*)&sA[lk + 4][2 * lr] = pk2(q1.x, q1.x);
        *(ull*)&sA[lk + 5][2 * lr] = pk2(q1.y, q1.y);
        *(ull*)&sA[lk + 6][2 * lr] = pk2(q1.z, q1.z);
        *(ull*)&sA[lk + 7][2 * lr] = pk2(q1.w, q1.w);

        const float* bp = kb + (size_t)(m0 + lr) * D_ + k0 + lk;
        float4 k0v = *(const float4*)(bp);
        float4 k1v = *(const float4*)(bp + 4);
        sB[lk + 0][lr] = k0v.x;
        sB[lk + 1][lr] = k0v.y;
        sB[lk + 2][lr] = k0v.z;
        sB[lk + 3][lr] = k0v.w;
        sB[lk + 4][lr] = k1v.x;
        sB[lk + 5][lr] = k1v.y;
        sB[lk + 6][lr] = k1v.z;
        sB[lk + 7][lr] = k1v.w;
        __syncthreads();

        MAINLOOP_16(acc, sA, sB, ty, tx)
        __syncthreads();
    }

    float* Sb = g_attn + (size_t)b * N_ * N_;
#pragma unroll
    for (int i = 0; i < 8; ++i) {
        float2 p0 = up2(acc[i][0]), p1 = up2(acc[i][1]);
        float2 p2 = up2(acc[i][2]), p3 = up2(acc[i][3]);
        float* o = Sb + (size_t)(n0 + ty * 8 + i) * N_ + m0 + tx * 8;
        *(float4*)(o)     = make_float4(p0.x, p0.y, p1.x, p1.y);
        *(float4*)(o + 4) = make_float4(p2.x, p2.y, p3.x, p3.y);
    }
}

// ---------------------------------------------------------------------------
// Kernel 3: row softmax over g_attn, in place. One block per (b, n) row.
// ---------------------------------------------------------------------------
__global__ __launch_bounds__(256) void k_softmax()
{
    float* p = g_attn + (size_t)blockIdx.x * N_;
    const int t = threadIdx.x;
    const int w = t >> 5, l = t & 31;
    __shared__ float red[8];

    float4 v = *(float4*)(p + t * 4);
    float m = fmaxf(fmaxf(v.x, v.y), fmaxf(v.z, v.w));
#pragma unroll
    for (int o = 16; o; o >>= 1) m = fmaxf(m, __shfl_xor_sync(0xffffffffu, m, o));
    if (l == 0) red[w] = m;
    __syncthreads();
    if (t == 0) {
        float mm = red[0];
#pragma unroll
        for (int i = 1; i < 8; ++i) mm = fmaxf(mm, red[i]);
        red[0] = mm;
    }
    __syncthreads();
    const float M = red[0];
    __syncthreads();

    v.x = __expf(v.x - M);
    v.y = __expf(v.y - M);
    v.z = __expf(v.z - M);
    v.w = __expf(v.w - M);
    float s = v.x + v.y + v.z + v.w;
#pragma unroll
    for (int o = 16; o; o >>= 1) s += __shfl_xor_sync(0xffffffffu, s, o);
    if (l == 0) red[w] = s;
    __syncthreads();
    if (t == 0) {
        float ss = red[0];
#pragma unroll
        for (int i = 1; i < 8; ++i) ss += red[i];
        red[0] = ss;
    }
    __syncthreads();
    const float inv = 1.0f / red[0];

    v.x *= inv; v.y *= inv; v.z *= inv; v.w *= inv;
    *(float4*)(p + t * 4) = v;
}

// ---------------------------------------------------------------------------
// Kernel 4: out[b,c,n] = gamma * sum_m attn[b,n,m] * vT[b,m,c] + x[b,c,n]
// Tile 128(c) x 128(n), K = N_ = 1024.
// A (dup) = vT : c-contiguous -> vector dup staging.
// B = attn : m(k)-contiguous per n row -> transpose staging.
// ---------------------------------------------------------------------------
__global__ __launch_bounds__(256, 2) void k_out(
    const float* __restrict__ x, const float* __restrict__ gamma,
    float* __restrict__ out)
{
    __shared__ float sA[16][SA_STR];
    __shared__ float sB[16][SB_STR];

    const int b  = blockIdx.z;
    const int c0 = blockIdx.y * 128;
    const int n0 = blockIdx.x * 128;

    const int t  = threadIdx.x;
    const int tx = t & 15, ty = t >> 4;

    const int la_k = t >> 4;          // 0..15
    const int la_c = (t & 15) * 8;    // 0..120
    const int lb_n = t >> 1;          // 0..127
    const int lb_k = (t & 1) * 8;     // 0 or 8

    const float* vb = g_v    + (size_t)b * N_ * C_ + c0;
    const float* Ab = g_attn + (size_t)b * N_ * N_ + (size_t)(n0 + lb_n) * N_ + lb_k;

    ull acc[8][4];
#pragma unroll
    for (int i = 0; i < 8; ++i)
#pragma unroll
        for (int j = 0; j < 4; ++j) acc[i][j] = 0ULL;

    for (int k0 = 0; k0 < N_; k0 += 16) {
        const float* ap = vb + (size_t)(k0 + la_k) * C_ + la_c;
        float4 v0 = *(const float4*)(ap);
        float4 v1 = *(const float4*)(ap + 4);
        store_dup8(&sA[la_k][0], 2 * la_c, v0, v1);

        const float* bp = Ab + k0;
        float4 a0 = *(const float4*)(bp);
        float4 a1 = *(const float4*)(bp + 4);
        sB[lb_k + 0][lb_n] = a0.x;
        sB[lb_k + 1][lb_n] = a0.y;
        sB[lb_k + 2][lb_n] = a0.z;
        sB[lb_k + 3][lb_n] = a0.w;
        sB[lb_k + 4][lb_n] = a1.x;
        sB[lb_k + 5][lb_n] = a1.y;
        sB[lb_k + 6][lb_n] = a1.z;
        sB[lb_k + 7][lb_n] = a1.w;
        __syncthreads();

        MAINLOOP_16(acc, sA, sB, ty, tx)
        __syncthreads();
    }

    const float gm = gamma[0];
#pragma unroll
    for (int i = 0; i < 8; ++i) {
        int c = c0 + ty * 8 + i;
        size_t off = ((size_t)b * C_ + c) * N_ + n0 + tx * 8;
        float4 x0 = *(const float4*)(x + off);
        float4 x1 = *(const float4*)(x + off + 4);
        float2 p0 = up2(acc[i][0]), p1 = up2(acc[i][1]);
        float2 p2 = up2(acc[i][2]), p3 = up2(acc[i][3]);
        float4 o0, o1;
        o0.x = fmaf(gm, p0.x, x0.x);
        o0.y = fmaf(gm, p0.y, x0.y);
        o0.z = fmaf(gm, p1.x, x0.z);
        o0.w = fmaf(gm, p1.y, x0.w);
        o1.x = fmaf(gm, p2.x, x1.x);
        o1.y = fmaf(gm, p2.y, x1.y);
        o1.z = fmaf(gm, p3.x, x1.z);
        o1.w = fmaf(gm, p3.y, x1.w);
        *(float4*)(out + off)     = o0;
        *(float4*)(out + off + 4) = o1;
    }
}

// ---------------------------------------------------------------------------
extern "C" void kernel_launch(void* const* d_in, const int* in_sizes, int n_in,
                              void* d_out, int out_size)
{
    (void)in_sizes; (void)n_in; (void)out_size;
    const float* x     = (const float*)d_in[0];
    const float* Wq    = (const float*)d_in[1];
    const float* bq    = (const float*)d_in[2];
    const float* Wk    = (const float*)d_in[3];
    const float* bk    = (const float*)d_in[4];
    const float* Wv    = (const float*)d_in[5];
    const float* bv    = (const float*)d_in[6];
    const float* gamma = (const float*)d_in[7];
    float* out = (float*)d_out;

    k_proj  <<<dim3(N_ / 128, 5,        B_), 256>>>(x, Wq, bq, Wk, bk, Wv, bv);
    k_scores<<<dim3(N_ / 128, N_ / 128, B_), 256>>>();
    k_softmax<<<B_ * N_, 256>>>();
    k_out   <<<dim3(N_ / 128, C_ / 128, B_), 256>>>(x, gamma, out);
}